// round 5
// baseline (speedup 1.0000x reference)
#include <cuda_runtime.h>
#include <cstdint>

// Embedding gather: out[t, :] = weights[ids[t], :]
// ids: 16384 int32, weights: [50257,1024] fp32, out: [16384,1024] fp32
//
// Block = 256 threads (one float4-column each); each block handles 8 tokens.
// Each thread front-batches 8 independent LDG.128 (MLP_p1=8) before storing.
// Streaming stores (.cs) keep L2 capacity for gathered weight-row reuse --
// measured DRAM traffic is ~compulsory-read only (~69MB), output parks in L2.

static constexpr int ROW_F4      = 256;  // float4 per row (1024 floats)
static constexpr int TOK_PER_BLK = 8;

__global__ void __launch_bounds__(256) embed_gather_kernel(
    const int* __restrict__ ids,
    const float4* __restrict__ w,
    float4* __restrict__ out,
    int n_tokens)
{
    const int col  = threadIdx.x;                 // 0..255
    const int tok0 = blockIdx.x * TOK_PER_BLK;

    if (tok0 + TOK_PER_BLK <= n_tokens) {
        int rows[TOK_PER_BLK];
        #pragma unroll
        for (int i = 0; i < TOK_PER_BLK; ++i)
            rows[i] = __ldg(ids + tok0 + i);

        float4 v[TOK_PER_BLK];
        #pragma unroll
        for (int i = 0; i < TOK_PER_BLK; ++i)
            v[i] = __ldg(w + (size_t)rows[i] * ROW_F4 + col);

        #pragma unroll
        for (int i = 0; i < TOK_PER_BLK; ++i)
            __stcs(out + (size_t)(tok0 + i) * ROW_F4 + col, v[i]);
    } else {
        for (int t = tok0; t < n_tokens; ++t) {
            int r = __ldg(ids + t);
            __stcs(out + (size_t)t * ROW_F4 + col,
                   __ldg(w + (size_t)r * ROW_F4 + col));
        }
    }
}

extern "C" void kernel_launch(void* const* d_in, const int* in_sizes, int n_in,
                              void* d_out, int out_size)
{
    const int*    ids = (const int*)d_in[0];
    const float4* w   = (const float4*)d_in[1];
    float4*       out = (float4*)d_out;

    int n_tokens = in_sizes[0];                                  // 16384
    int blocks   = (n_tokens + TOK_PER_BLK - 1) / TOK_PER_BLK;   // 2048
    embed_gather_kernel<<<blocks, 256>>>(ids, w, out, n_tokens);
}